// round 6
// baseline (speedup 1.0000x reference)
#include <cuda_runtime.h>
#include <cstdint>

// Problem constants
constexpr int B_   = 16;
constexpr int NH   = 64;
constexpr int NW   = 64;
constexpr int DO   = 768;
constexpr int KH   = 16;
constexpr int KW   = 16;
constexpr int H_   = 512;
constexpr int WF   = 512;

constexpr int M_ = B_ * NH * NW;   // 65536
constexpr int N_ = KH * KW;        // 256
constexpr int K_ = DO;             // 768

// GEMM tiling
constexpr int BM = 128, BN = 128, BK = 32;
constexpr int NTILES = K_ / BK;    // 24
constexpr int APAD = 36;

// 64 MB scratch: proj[m][n], m = ((b*64+h)*64+w), n = dh*16+dw
__device__ float g_proj[(size_t)M_ * N_];

__device__ __forceinline__ uint32_t f2tf32(float x) {
    uint32_t r;
    asm volatile("cvt.rna.tf32.f32 %0, %1;" : "=r"(r) : "f"(x));
    return r;
}

#define MMA_TF32(d, a, b)                                                         \
    asm volatile(                                                                 \
        "mma.sync.aligned.m16n8k8.row.col.f32.tf32.tf32.f32 "                     \
        "{%0,%1,%2,%3}, {%4,%5,%6,%7}, {%8,%9}, {%0,%1,%2,%3};\n"                 \
        : "+f"(d[0]), "+f"(d[1]), "+f"(d[2]), "+f"(d[3])                          \
        : "r"(a[0]), "r"(a[1]), "r"(a[2]), "r"(a[3]), "r"(b[0]), "r"(b[1]))

// proj = tgt[M,K] @ W[N,K]^T
__global__ __launch_bounds__(256) void gemm_tf32_kernel(
    const float* __restrict__ A, const float* __restrict__ Bw) {
    extern __shared__ float smem[];
    float* As = smem;                       // [2][128][APAD]
    float* Bs = smem + 2 * BM * APAD;       // [2][128][APAD]

    const int tid  = threadIdx.x;
    const int bN   = blockIdx.x * BN;
    const int bM   = blockIdx.y * BM;

    const int warp = tid >> 5;
    const int lane = tid & 31;
    const int wM   = (warp & 1) * 64;
    const int wN   = (warp >> 1) * 32;
    const int grp  = lane >> 2;
    const int tig  = lane & 3;

    const int lrow = tid >> 3;
    const int lcol = (tid & 7) * 4;

    float4 ra[4], rb[4];

    auto load_tile = [&](int t) {
        const int k0 = t * BK;
        #pragma unroll
        for (int p = 0; p < 4; ++p) {
            const int r = p * 32 + lrow;
            ra[p] = *(const float4*)(A  + (size_t)(bM + r) * K_ + k0 + lcol);
            rb[p] = *(const float4*)(Bw + (size_t)(bN + r) * K_ + k0 + lcol);
        }
    };
    auto store_tile = [&](int buf) {
        float* as = As + buf * BM * APAD;
        float* bs = Bs + buf * BM * APAD;
        #pragma unroll
        for (int p = 0; p < 4; ++p) {
            const int r = p * 32 + lrow;
            float4 va = ra[p], vb = rb[p];
            va.x = __uint_as_float(f2tf32(va.x)); va.y = __uint_as_float(f2tf32(va.y));
            va.z = __uint_as_float(f2tf32(va.z)); va.w = __uint_as_float(f2tf32(va.w));
            vb.x = __uint_as_float(f2tf32(vb.x)); vb.y = __uint_as_float(f2tf32(vb.y));
            vb.z = __uint_as_float(f2tf32(vb.z)); vb.w = __uint_as_float(f2tf32(vb.w));
            *(float4*)(as + r * APAD + lcol) = va;
            *(float4*)(bs + r * APAD + lcol) = vb;
        }
    };

    float acc[4][4][4];
    #pragma unroll
    for (int i = 0; i < 4; ++i)
        #pragma unroll
        for (int j = 0; j < 4; ++j)
            #pragma unroll
            for (int r = 0; r < 4; ++r) acc[i][j][r] = 0.f;

    load_tile(0);
    store_tile(0);
    __syncthreads();

    for (int t = 0; t < NTILES; ++t) {
        const int buf = t & 1;
        if (t + 1 < NTILES) load_tile(t + 1);

        const float* as = As + buf * BM * APAD;
        const float* bs = Bs + buf * BM * APAD;
        #pragma unroll
        for (int kk = 0; kk < 4; ++kk) {
            const int k0 = kk * 8;
            uint32_t af[4][4], bf[4][2];
            #pragma unroll
            for (int i = 0; i < 4; ++i) {
                const float* p0 = as + (wM + i * 16 + grp) * APAD + k0 + tig;
                af[i][0] = __float_as_uint(p0[0]);
                af[i][2] = __float_as_uint(p0[4]);
                const float* p1 = p0 + 8 * APAD;
                af[i][1] = __float_as_uint(p1[0]);
                af[i][3] = __float_as_uint(p1[4]);
            }
            #pragma unroll
            for (int j = 0; j < 4; ++j) {
                const float* p0 = bs + (wN + j * 8 + grp) * APAD + k0 + tig;
                bf[j][0] = __float_as_uint(p0[0]);
                bf[j][1] = __float_as_uint(p0[4]);
            }
            #pragma unroll
            for (int i = 0; i < 4; ++i)
                #pragma unroll
                for (int j = 0; j < 4; ++j)
                    MMA_TF32(acc[i][j], af[i], bf[j]);
        }
        if (t + 1 < NTILES) store_tile(1 - buf);
        __syncthreads();
    }

    // epilogue: contiguous [m][n] stores (fully coalesced)
    #pragma unroll
    for (int i = 0; i < 4; ++i) {
        const int r0 = bM + wM + i * 16 + grp;
        #pragma unroll
        for (int j = 0; j < 4; ++j) {
            const int c0 = bN + wN + j * 8 + tig * 2;
            *(float2*)(g_proj + (size_t)r0 * N_ + c0) =
                make_float2(acc[i][j][0], acc[i][j][1]);
            *(float2*)(g_proj + (size_t)(r0 + 8) * N_ + c0) =
                make_float2(acc[i][j][2], acc[i][j][3]);
        }
    }
}

// ---------------- fold ----------------
__device__ __forceinline__ float4 f4add(float4 a, float4 b) {
    return make_float4(a.x + b.x, a.y + b.y, a.z + b.z, a.w + b.w);
}

// Generic scalar path for edge pixels (y==511 row, x==511 column).
__device__ __noinline__ float fold_pix(const float* __restrict__ pb, int y, int x) {
    int hy[10], dy[10]; int cy = 0;
    {
        const int Y = y >> 3, py = y & 7;
        hy[cy] = Y; dy[cy] = py; ++cy;
        if (Y > 0) { hy[cy] = Y - 1; dy[cy] = py + 8; ++cy; }
        if (y == H_ - 1)
            for (int d = 8; d <= 15; ++d) { hy[cy] = NH - 1; dy[cy] = d; ++cy; }
    }
    int hx[10], dx[10]; int cx = 0;
    {
        const int X = x >> 3, px = x & 7;
        hx[cx] = X; dx[cx] = px; ++cx;
        if (X > 0) { hx[cx] = X - 1; dx[cx] = px + 8; ++cx; }
        if (x == WF - 1)
            for (int d = 8; d <= 15; ++d) { hx[cx] = NW - 1; dx[cx] = d; ++cx; }
    }
    float s = 0.f;
    for (int i = 0; i < cy; ++i) {
        const float* r = pb + ((size_t)(hy[i] * 64) << 8) + dy[i] * 16;
        for (int j = 0; j < cx; ++j)
            s += r[(hx[j] << 8) + dx[j]];
    }
    return s / (float)(cy * cx);
}

// One thread per 4x4 pixel block: up to 16 independent float4 loads (MLP=16),
// 4 coalesced float4 stores. y0, x0 are 4-aligned so the whole block shares
// (Y, X) and the X>0 / Y>0 predicates.
__global__ __launch_bounds__(256) void fold_kernel(float* __restrict__ out) {
    const int t   = blockIdx.x * blockDim.x + threadIdx.x;   // 262,144 threads
    const int b   = t >> 14;
    const int rem = t & 16383;
    const int yq  = rem >> 7;          // 0..127, y0 = yq*4
    const int xq  = rem & 127;         // x0 = xq*4
    const int y0  = yq << 2;
    const int x0  = xq << 2;

    const float* pb = g_proj + ((size_t)b << 20);            // b * 4096 * 256
    float* op = out + ((size_t)b << 18) + (y0 << 9) + x0;

    if (yq == 127 || xq == 127) {      // edge fallback (~1.5% of threads)
        #pragma unroll
        for (int r = 0; r < 4; ++r) {
            float4 s;
            s.x = fold_pix(pb, y0 + r, x0);
            s.y = fold_pix(pb, y0 + r, x0 + 1);
            s.z = fold_pix(pb, y0 + r, x0 + 2);
            s.w = fold_pix(pb, y0 + r, x0 + 3);
            *(float4*)(op + r * WF) = s;
        }
        return;
    }

    const int Y   = yq >> 1;
    const int py0 = (yq & 1) << 2;     // 0 or 4
    const int X   = xq >> 1;
    const int px  = (xq & 1) << 2;     // 0 or 4
    // base points at proj[(b,Y,X)][py0*16+px]
    const float* prow = pb + ((size_t)(Y * 64 + X) << 8) + py0 * 16 + px;

    const bool hasX = (X > 0), hasY = (Y > 0);

    float4 v0[4], v1[4], v2[4], v3[4];
    #pragma unroll
    for (int r = 0; r < 4; ++r)
        v0[r] = __ldg((const float4*)(prow + r * 16));                    // (Y,X)
    if (hasX) {
        #pragma unroll
        for (int r = 0; r < 4; ++r)
            v1[r] = __ldg((const float4*)(prow - 248 + r * 16));          // (Y,X-1)
    }
    if (hasY) {
        const float* pu = prow - 16256;                                    // (Y-1,X)
        #pragma unroll
        for (int r = 0; r < 4; ++r)
            v2[r] = __ldg((const float4*)(pu + r * 16));
        if (hasX) {
            #pragma unroll
            for (int r = 0; r < 4; ++r)
                v3[r] = __ldg((const float4*)(pu - 248 + r * 16));        // (Y-1,X-1)
        }
    }

    const float inv = 1.0f / (float)((hasX ? 2 : 1) * (hasY ? 2 : 1));
    #pragma unroll
    for (int r = 0; r < 4; ++r) {
        float4 s = v0[r];
        if (hasX) s = f4add(s, v1[r]);
        if (hasY) {
            s = f4add(s, v2[r]);
            if (hasX) s = f4add(s, v3[r]);
        }
        s.x *= inv; s.y *= inv; s.z *= inv; s.w *= inv;
        *(float4*)(op + r * WF) = s;
    }
}

extern "C" void kernel_launch(void* const* d_in, const int* in_sizes, int n_in,
                              void* d_out, int out_size) {
    const float* tgt    = (const float*)d_in[0];   // [16, 4096, 768]
    const float* weight = (const float*)d_in[1];   // [256, 768]
    float* out = (float*)d_out;                    // [16, 512, 512]

    const int smem_bytes = 2 * 2 * BM * APAD * (int)sizeof(float);  // 73728
    cudaFuncSetAttribute(gemm_tf32_kernel,
                         cudaFuncAttributeMaxDynamicSharedMemorySize, smem_bytes);

    dim3 grid(N_ / BN, M_ / BM);   // (2, 512)
    gemm_tf32_kernel<<<grid, 256, smem_bytes>>>(tgt, weight);

    const int nthreads = B_ * (H_ / 4) * (WF / 4);  // 262,144
    fold_kernel<<<nthreads / 256, 256>>>(out);
}

// round 7
// speedup vs baseline: 1.0652x; 1.0652x over previous
#include <cuda_runtime.h>
#include <cstdint>

// Problem constants
constexpr int B_   = 16;
constexpr int NH   = 64;
constexpr int NW   = 64;
constexpr int DO   = 768;
constexpr int KH   = 16;
constexpr int KW   = 16;
constexpr int H_   = 512;
constexpr int WF   = 512;

constexpr int M_ = B_ * NH * NW;   // 65536
constexpr int N_ = KH * KW;        // 256
constexpr int K_ = DO;             // 768

// GEMM tiling
constexpr int BM = 128, BN = 128, BK = 32;
constexpr int NTILES = K_ / BK;    // 24
constexpr int APAD = 36;

// 64 MB scratch: proj[m][n], m = ((b*64+h)*64+w), n = dh*16+dw
__device__ float g_proj[(size_t)M_ * N_];

__device__ __forceinline__ uint32_t f2tf32(float x) {
    uint32_t r;
    asm volatile("cvt.rna.tf32.f32 %0, %1;" : "=r"(r) : "f"(x));
    return r;
}

#define MMA_TF32(d, a, b)                                                         \
    asm volatile(                                                                 \
        "mma.sync.aligned.m16n8k8.row.col.f32.tf32.tf32.f32 "                     \
        "{%0,%1,%2,%3}, {%4,%5,%6,%7}, {%8,%9}, {%0,%1,%2,%3};\n"                 \
        : "+f"(d[0]), "+f"(d[1]), "+f"(d[2]), "+f"(d[3])                          \
        : "r"(a[0]), "r"(a[1]), "r"(a[2]), "r"(a[3]), "r"(b[0]), "r"(b[1]))

// proj = tgt[M,K] @ W[N,K]^T
__global__ __launch_bounds__(256) void gemm_tf32_kernel(
    const float* __restrict__ A, const float* __restrict__ Bw) {
    extern __shared__ float smem[];
    float* As = smem;                       // [2][128][APAD]
    float* Bs = smem + 2 * BM * APAD;       // [2][128][APAD]

    const int tid  = threadIdx.x;
    const int bN   = blockIdx.x * BN;
    const int bM   = blockIdx.y * BM;

    const int warp = tid >> 5;
    const int lane = tid & 31;
    const int wM   = (warp & 1) * 64;
    const int wN   = (warp >> 1) * 32;
    const int grp  = lane >> 2;
    const int tig  = lane & 3;

    const int lrow = tid >> 3;
    const int lcol = (tid & 7) * 4;

    float4 ra[4], rb[4];

    auto load_tile = [&](int t) {
        const int k0 = t * BK;
        #pragma unroll
        for (int p = 0; p < 4; ++p) {
            const int r = p * 32 + lrow;
            ra[p] = *(const float4*)(A  + (size_t)(bM + r) * K_ + k0 + lcol);
            rb[p] = *(const float4*)(Bw + (size_t)(bN + r) * K_ + k0 + lcol);
        }
    };
    auto store_tile = [&](int buf) {
        float* as = As + buf * BM * APAD;
        float* bs = Bs + buf * BM * APAD;
        #pragma unroll
        for (int p = 0; p < 4; ++p) {
            const int r = p * 32 + lrow;
            float4 va = ra[p], vb = rb[p];
            va.x = __uint_as_float(f2tf32(va.x)); va.y = __uint_as_float(f2tf32(va.y));
            va.z = __uint_as_float(f2tf32(va.z)); va.w = __uint_as_float(f2tf32(va.w));
            vb.x = __uint_as_float(f2tf32(vb.x)); vb.y = __uint_as_float(f2tf32(vb.y));
            vb.z = __uint_as_float(f2tf32(vb.z)); vb.w = __uint_as_float(f2tf32(vb.w));
            *(float4*)(as + r * APAD + lcol) = va;
            *(float4*)(bs + r * APAD + lcol) = vb;
        }
    };

    float acc[4][4][4];
    #pragma unroll
    for (int i = 0; i < 4; ++i)
        #pragma unroll
        for (int j = 0; j < 4; ++j)
            #pragma unroll
            for (int r = 0; r < 4; ++r) acc[i][j][r] = 0.f;

    load_tile(0);
    store_tile(0);
    __syncthreads();

    for (int t = 0; t < NTILES; ++t) {
        const int buf = t & 1;
        if (t + 1 < NTILES) load_tile(t + 1);

        const float* as = As + buf * BM * APAD;
        const float* bs = Bs + buf * BM * APAD;
        #pragma unroll
        for (int kk = 0; kk < 4; ++kk) {
            const int k0 = kk * 8;
            uint32_t af[4][4], bf[4][2];
            #pragma unroll
            for (int i = 0; i < 4; ++i) {
                const float* p0 = as + (wM + i * 16 + grp) * APAD + k0 + tig;
                af[i][0] = __float_as_uint(p0[0]);
                af[i][2] = __float_as_uint(p0[4]);
                const float* p1 = p0 + 8 * APAD;
                af[i][1] = __float_as_uint(p1[0]);
                af[i][3] = __float_as_uint(p1[4]);
            }
            #pragma unroll
            for (int j = 0; j < 4; ++j) {
                const float* p0 = bs + (wN + j * 8 + grp) * APAD + k0 + tig;
                bf[j][0] = __float_as_uint(p0[0]);
                bf[j][1] = __float_as_uint(p0[4]);
            }
            #pragma unroll
            for (int i = 0; i < 4; ++i)
                #pragma unroll
                for (int j = 0; j < 4; ++j)
                    MMA_TF32(acc[i][j], af[i], bf[j]);
        }
        if (t + 1 < NTILES) store_tile(1 - buf);
        __syncthreads();
    }

    // epilogue: contiguous [m][n] stores (fully coalesced)
    #pragma unroll
    for (int i = 0; i < 4; ++i) {
        const int r0 = bM + wM + i * 16 + grp;
        #pragma unroll
        for (int j = 0; j < 4; ++j) {
            const int c0 = bN + wN + j * 8 + tig * 2;
            *(float2*)(g_proj + (size_t)r0 * N_ + c0) =
                make_float2(acc[i][j][0], acc[i][j][1]);
            *(float2*)(g_proj + (size_t)(r0 + 8) * N_ + c0) =
                make_float2(acc[i][j][2], acc[i][j][3]);
        }
    }
}

// ---------------- fold main: one thread per 2 pixels, branch-light ----------------
// Values written at y==511 or x==511 are later overwritten by fold_edge_kernel.
__global__ __launch_bounds__(256) void fold_main_kernel(float* __restrict__ out) {
    const int t   = blockIdx.x * blockDim.x + threadIdx.x;   // 2,097,152 threads
    const int b   = t >> 17;
    const int rem = t & 131071;
    const int y   = rem >> 8;          // 0..511
    const int xq  = rem & 255;         // x0 = xq*2
    const int x0  = xq << 1;

    const int Y  = y >> 3,  py = y & 7;
    const int X  = x0 >> 3, px = x0 & 7;   // px in {0,2,4,6}

    const float* base =
        g_proj + (((size_t)((b << 6 | Y) << 6 | X)) << 8) + py * 16 + px;

    const bool hasX = (X > 0), hasY = (Y > 0);

    float2 s = *(const float2*)base;                       // (Y, X)
    if (hasX) {                                            // (Y, X-1): m-1, n+8
        float2 v = *(const float2*)(base - 248);
        s.x += v.x; s.y += v.y;
    }
    if (hasY) {                                            // (Y-1, X): m-64, n+128
        const float* pu = base - 16384 + 128;
        float2 v = *(const float2*)pu;
        s.x += v.x; s.y += v.y;
        if (hasX) {                                        // (Y-1, X-1)
            float2 w = *(const float2*)(pu - 248);
            s.x += w.x; s.y += w.y;
        }
    }
    const float inv = 1.0f /
        (float)((hasX ? 2 : 1) * (hasY ? 2 : 1));
    s.x *= inv; s.y *= inv;
    *(float2*)(out + ((size_t)b << 18) + (y << 9) + x0) = s;
}

// ---------------- fold edge: overwrite y==511 row and x==511 column ----------------
__global__ __launch_bounds__(256) void fold_edge_kernel(float* __restrict__ out) {
    const int t = blockIdx.x * blockDim.x + threadIdx.x;   // 16384 threads
    const int b = t >> 10;
    const int r = t & 1023;
    int y, x;
    if (r < 512) { y = H_ - 1; x = r; }        // last row
    else         { y = r - 512; x = WF - 1; }  // last column (y=511 done twice, same value)

    int hy[10], dy[10]; int cy = 0;
    {
        const int Y = y >> 3, py = y & 7;
        hy[cy] = Y; dy[cy] = py; ++cy;
        if (Y > 0) { hy[cy] = Y - 1; dy[cy] = py + 8; ++cy; }
        if (y == H_ - 1)
            for (int d = 8; d <= 15; ++d) { hy[cy] = NH - 1; dy[cy] = d; ++cy; }
    }
    int hx[10], dx[10]; int cx = 0;
    {
        const int X = x >> 3, px = x & 7;
        hx[cx] = X; dx[cx] = px; ++cx;
        if (X > 0) { hx[cx] = X - 1; dx[cx] = px + 8; ++cx; }
        if (x == WF - 1)
            for (int d = 8; d <= 15; ++d) { hx[cx] = NW - 1; dx[cx] = d; ++cx; }
    }

    const float* pb = g_proj + ((size_t)b << 20);
    float s = 0.f;
    for (int i = 0; i < cy; ++i) {
        const float* row = pb + ((size_t)(hy[i] * 64) << 8) + dy[i] * 16;
        for (int j = 0; j < cx; ++j)
            s += row[(hx[j] << 8) + dx[j]];
    }
    out[((size_t)b << 18) + (y << 9) + x] = s / (float)(cy * cx);
}

extern "C" void kernel_launch(void* const* d_in, const int* in_sizes, int n_in,
                              void* d_out, int out_size) {
    const float* tgt    = (const float*)d_in[0];   // [16, 4096, 768]
    const float* weight = (const float*)d_in[1];   // [256, 768]
    float* out = (float*)d_out;                    // [16, 512, 512]

    const int smem_bytes = 2 * 2 * BM * APAD * (int)sizeof(float);  // 73728
    cudaFuncSetAttribute(gemm_tf32_kernel,
                         cudaFuncAttributeMaxDynamicSharedMemorySize, smem_bytes);

    dim3 grid(N_ / BN, M_ / BM);   // (2, 512)
    gemm_tf32_kernel<<<grid, 256, smem_bytes>>>(tgt, weight);

    const int main_threads = B_ * H_ * (WF / 2);   // 2,097,152
    fold_main_kernel<<<main_threads / 256, 256>>>(out);

    fold_edge_kernel<<<(B_ * 1024) / 256, 256>>>(out);   // 64 blocks
}